// round 17
// baseline (speedup 1.0000x reference)
#include <cuda_runtime.h>
#include <cuda_fp16.h>
#include <math.h>
#include <cstdint>

#define B_    4
#define T_    2048
#define DM    1024
#define NH    16
#define NKV   4
#define DK    64
#define ROWS  (B_ * T_)          // 8192
#define KVD   (NKV * DK)         // 256
#define NQKV  (DM + 2 * KVD)     // 1536
#define NWALL (NQKV + DM)        // 2560 packed weight rows

// ---------------- scratch (static device globals; no allocation) ----------------
__device__ __half g_Xhi[(size_t)ROWS * DM];
__device__ __half g_Ahi[(size_t)ROWS * DM];
__device__ __half g_Qhi[(size_t)ROWS * DM];
__device__ __half g_Khi[(size_t)ROWS * KVD];
__device__ __half g_Vhi[(size_t)ROWS * KVD];
__device__ __half g_Wall[(size_t)NWALL * DM];   // rows 0..1535 Wqkv^T, 1536..2559 Wo^T
__device__ float2 g_rope[(size_t)T_ * 32];      // (cos, sin) per (t, freq)

// ================= helpers =================
__device__ __forceinline__ uint32_t smem_u32(const void* p) {
    uint32_t a;
    asm("{ .reg .u64 t; cvta.to.shared.u64 t, %1; cvt.u32.u64 %0, t; }" : "=r"(a) : "l"(p));
    return a;
}

#define LDSM4(r0, r1, r2, r3, addr)                                              \
    asm volatile("ldmatrix.sync.aligned.m8n8.x4.shared.b16 {%0,%1,%2,%3}, [%4];" \
                 : "=r"(r0), "=r"(r1), "=r"(r2), "=r"(r3) : "r"(addr))
#define LDSM4T(r0, r1, r2, r3, addr)                                                   \
    asm volatile("ldmatrix.sync.aligned.m8n8.x4.trans.shared.b16 {%0,%1,%2,%3}, [%4];" \
                 : "=r"(r0), "=r"(r1), "=r"(r2), "=r"(r3) : "r"(addr))

__device__ __forceinline__ void mma_f16(float* c, const uint32_t* a, const uint32_t* b) {
    asm volatile(
        "mma.sync.aligned.m16n8k16.row.col.f32.f16.f16.f32 "
        "{%0,%1,%2,%3}, {%4,%5,%6,%7}, {%8,%9}, {%0,%1,%2,%3};"
        : "+f"(c[0]), "+f"(c[1]), "+f"(c[2]), "+f"(c[3])
        : "r"(a[0]), "r"(a[1]), "r"(a[2]), "r"(a[3]), "r"(b[0]), "r"(b[1]));
}

#define CP_ASYNC16(saddr, gptr) \
    asm volatile("cp.async.cg.shared.global [%0], [%1], 16;" :: "r"(saddr), "l"(gptr))
#define CP_COMMIT() asm volatile("cp.async.commit_group;" ::: "memory")
#define CP_WAIT(n)  asm volatile("cp.async.wait_group %0;" :: "n"(n) : "memory")

__device__ __forceinline__ uint32_t pack_hi(float a, float b) {
    __half2 h = __floats2half2_rn(a, b);
    return *reinterpret_cast<uint32_t*>(&h);
}

// ---------------- RoPE cos/sin table (invfreq computed inline in fp64) ----------------
__global__ void rope_table_kernel() {
    int idx = blockIdx.x * blockDim.x + threadIdx.x;
    if (idx >= T_ * 32) return;
    int t = idx >> 5, i = idx & 31;
    float invf = (float)(1.0 / pow(10000.0, (double)(2 * i) / (double)DK));
    float angle = (float)t * invf;
    float s, c;
    sincosf(angle, &s, &c);
    g_rope[idx] = make_float2(c, s);
}

// ---------------- fp32 -> fp16, 8 elements/thread, fully vectorized ----------------
__global__ void cvt_hi8(const float* __restrict__ in, __half* __restrict__ hi, int n8) {
    int i = blockIdx.x * blockDim.x + threadIdx.x;
    if (i >= n8) return;
    float4 a = ((const float4*)in)[2 * i];
    float4 b = ((const float4*)in)[2 * i + 1];
    uint4 o;
    o.x = pack_hi(a.x, a.y);
    o.y = pack_hi(a.z, a.w);
    o.z = pack_hi(b.x, b.y);
    o.w = pack_hi(b.z, b.w);
    ((uint4*)hi)[i] = o;
}

// ---------------- all weights: tiled transpose+convert into packed [NWALL][DM] ----------------
__global__ void cvt_w_all(const float* __restrict__ Wq, const float* __restrict__ Wk,
                          const float* __restrict__ Wv, const float* __restrict__ Wo,
                          __half* __restrict__ out) {
    __shared__ float tile[32][33];
    const int rt = blockIdx.x * 32;
    const int kt = blockIdx.y * 32;
    const int tx = threadIdx.x;
    const int ty = threadIdx.y;

    const float* src;
    int cb, ldn;
    if (rt < DM)             { src = Wq; cb = rt;              ldn = DM;  }
    else if (rt < DM + KVD)  { src = Wk; cb = rt - DM;         ldn = KVD; }
    else if (rt < NQKV)      { src = Wv; cb = rt - DM - KVD;   ldn = KVD; }
    else                     { src = Wo; cb = rt - NQKV;       ldn = DM;  }

#pragma unroll
    for (int i = 0; i < 4; i++) {
        int k = kt + ty + i * 8;
        tile[ty + i * 8][tx] = src[(size_t)k * ldn + cb + tx];
    }
    __syncthreads();
#pragma unroll
    for (int i = 0; i < 4; i++) {
        int r = rt + ty + i * 8;
        out[(size_t)r * DM + kt + tx] = __float2half_rn(tile[tx][ty + i * 8]);
    }
}

// ================= fp16 single-pass GEMM mainloop (BK=32, 3-stage cp.async) =================
#define G2LD 40
#define S_BHI 10240
#define G2_STAGE 20480
#define GEMM_SMEM (3 * G2_STAGE)   // 61440 B -> 2 CTAs/SM
#define QSCALE (0.125f * 1.4426950408889634f)

struct GemmCore {
    float acc[2][8][4];
};

__device__ __forceinline__ void gemm_mainloop(
    const __half* __restrict__ Ahi, const __half* __restrict__ Bhi,
    int m0, int n0, int K, uint32_t sb, GemmCore& g) {
    const int tid  = threadIdx.x;
    const int wid  = tid >> 5;
    const int lane = tid & 31;
    const int wm = (wid & 3) * 32;
    const int wn = (wid >> 2) * 64;

#pragma unroll
    for (int mi = 0; mi < 2; mi++)
#pragma unroll
        for (int ni = 0; ni < 8; ni++)
#pragma unroll
            for (int q = 0; q < 4; q++) g.acc[mi][ni][q] = 0.f;

    const int a_row  = wm + (lane & 15);
    const int a_colp = (lane >> 4) * 8;
    const int b_row  = wn + ((lane >> 4) << 3) + (lane & 7);
    const int b_colp = ((lane >> 3) & 1) * 8;

    const int nkt = K >> 5;

    auto issue = [&](int kt, int stg) {
        uint32_t sbase = sb + stg * G2_STAGE;
#pragma unroll
        for (int it = 0; it < 2; it++) {
            int idx = tid + it * 256;
            int r = idx >> 2;
            int c = idx & 3;
            uint32_t soff = sbase + (uint32_t)(r * 80 + c * 16);
            size_t ga = (size_t)(m0 + r) * K + kt + c * 8;
            size_t gb = (size_t)(n0 + r) * K + kt + c * 8;
            CP_ASYNC16(soff,          Ahi + ga);
            CP_ASYNC16(soff + S_BHI,  Bhi + gb);
        }
        CP_COMMIT();
    };

    issue(0, 0);
    if (nkt > 1) issue(32, 1);
    for (int ki = 0; ki < nkt; ki++) {
        if (ki + 2 < nkt) {
            issue((ki + 2) * 32, (ki + 2) % 3);
            CP_WAIT(2);
        } else if (ki + 1 < nkt) {
            CP_WAIT(1);
        } else {
            CP_WAIT(0);
        }
        __syncthreads();

        const uint32_t stg = sb + (ki % 3) * G2_STAGE;
#pragma unroll
        for (int kk = 0; kk < 2; kk++) {
            uint32_t ah[2][4];
#pragma unroll
            for (int mi = 0; mi < 2; mi++) {
                uint32_t addr = stg + (uint32_t)((a_row + mi * 16) * G2LD + kk * 16 + a_colp) * 2;
                LDSM4(ah[mi][0], ah[mi][1], ah[mi][2], ah[mi][3], addr);
            }
#pragma unroll
            for (int np = 0; np < 4; np++) {
                uint32_t addr = stg + S_BHI +
                                (uint32_t)((b_row + np * 16) * G2LD + kk * 16 + b_colp) * 2;
                uint32_t bh[4];
                LDSM4(bh[0], bh[1], bh[2], bh[3], addr);
#pragma unroll
                for (int mi = 0; mi < 2; mi++) {
                    mma_f16(g.acc[mi][2 * np],     ah[mi], bh);
                    mma_f16(g.acc[mi][2 * np + 1], ah[mi], bh + 2);
                }
            }
        }
        __syncthreads();
    }
}

__global__ __launch_bounds__(256, 2) void gemm_qkv(
    const __half* __restrict__ Ahi, const __half* __restrict__ Bhi,
    __half* __restrict__ Qhi, __half* __restrict__ Khi, __half* __restrict__ Vhi) {
    extern __shared__ char gsm[];
    const uint32_t sb = smem_u32(gsm);
    const int tid  = threadIdx.x;
    const int wid  = tid >> 5;
    const int lane = tid & 31;
    const int m0 = blockIdx.y * 128;
    const int n0 = blockIdx.x * 128;
    const int wm = (wid & 3) * 32;
    const int wn = (wid >> 2) * 64;

    GemmCore g;
    gemm_mainloop(Ahi, Bhi, m0, n0, DM, sb, g);

    const int er = (lane >> 2);
    const int ec = (lane & 3) * 2;
    const int kind = (n0 < DM) ? 0 : (n0 < DM + KVD ? 1 : 2);

    if (kind == 2) {
#pragma unroll
        for (int mi = 0; mi < 2; mi++) {
            int row = m0 + wm + mi * 16 + er;
#pragma unroll
            for (int ni = 0; ni < 8; ni++) {
                int colv = n0 - DM - KVD + wn + ni * 8 + ec;
                *(uint32_t*)(Vhi + (size_t)row * KVD + colv) =
                    pack_hi(g.acc[mi][ni][0], g.acc[mi][ni][1]);
                *(uint32_t*)(Vhi + (size_t)(row + 8) * KVD + colv) =
                    pack_hi(g.acc[mi][ni][2], g.acc[mi][ni][3]);
            }
        }
    } else {
        const float scale = (kind == 0) ? QSCALE : 1.0f;
        __half* Dhi = (kind == 0) ? Qhi : Khi;
        const int ldd = (kind == 0) ? DM : KVD;
        const int cb  = (kind == 0) ? n0 : n0 - DM;
#pragma unroll
        for (int mi = 0; mi < 2; mi++) {
            int row = m0 + wm + mi * 16 + er;
            int t0 = row & (T_ - 1);
            int t1 = (row + 8) & (T_ - 1);
#pragma unroll
            for (int ni = 0; ni < 8; ni++) {
                int col = cb + wn + ni * 8 + ec;
                int fidx = (col & 63) >> 1;
                float2 cs0 = g_rope[t0 * 32 + fidx];
                float2 cs1 = g_rope[t1 * 32 + fidx];
                float x1 = g.acc[mi][ni][0], x2 = g.acc[mi][ni][1];
                *(uint32_t*)(Dhi + (size_t)row * ldd + col) =
                    pack_hi((x1 * cs0.x - x2 * cs0.y) * scale,
                            (x1 * cs0.y + x2 * cs0.x) * scale);
                x1 = g.acc[mi][ni][2]; x2 = g.acc[mi][ni][3];
                *(uint32_t*)(Dhi + (size_t)(row + 8) * ldd + col) =
                    pack_hi((x1 * cs1.x - x2 * cs1.y) * scale,
                            (x1 * cs1.y + x2 * cs1.x) * scale);
            }
        }
    }
}

// ---------------- O-projection GEMM (fp32 out) ----------------
__global__ __launch_bounds__(256, 2) void gemm_mma(
    const __half* __restrict__ Ahi, const __half* __restrict__ Bhi,
    float* __restrict__ C, int M, int N, int K) {
    extern __shared__ char gsm[];
    const uint32_t sb = smem_u32(gsm);
    const int tid  = threadIdx.x;
    const int wid  = tid >> 5;
    const int lane = tid & 31;
    const int m0 = blockIdx.y * 128;
    const int n0 = blockIdx.x * 128;
    const int wm = (wid & 3) * 32;
    const int wn = (wid >> 2) * 64;

    GemmCore g;
    gemm_mainloop(Ahi, Bhi, m0, n0, K, sb, g);

    const int er = (lane >> 2);
    const int ec = (lane & 3) * 2;
#pragma unroll
    for (int mi = 0; mi < 2; mi++) {
        int row = m0 + wm + mi * 16 + er;
#pragma unroll
        for (int ni = 0; ni < 8; ni++) {
            int col = n0 + wn + ni * 8 + ec;
            *(float2*)(C + (size_t)row * N + col) =
                make_float2(g.acc[mi][ni][0], g.acc[mi][ni][1]);
            *(float2*)(C + (size_t)(row + 8) * N + col) =
                make_float2(g.acc[mi][ni][2], g.acc[mi][ni][3]);
        }
    }
}

// ================= Flash attention on mma.sync (fp16 single-pass), causal, GQA ===========
// 3-stage KV cp.async pipeline, 2 CTAs/SM.
#define FLD 72
#define F_QHI 0
#define F_KV0 9216
#define F_STAGE 9216
#define SK_HI 0
#define SV_HI 4608
#define FLASH_SMEM ((9216 + 3 * 9216) * 2)   // 73728 B

__global__ __launch_bounds__(256, 2) void flash_mma(
    const __half* __restrict__ Qhi,
    const __half* __restrict__ Khi, const __half* __restrict__ Vhi,
    __half* __restrict__ Ohi) {
    extern __shared__ __half fsm[];
    const uint32_t sb = smem_u32(fsm);

    const int tid  = threadIdx.x;
    const int wid  = tid >> 5;
    const int lane = tid & 31;
    const int bid = blockIdx.x;
    const int mt = 15 - (bid >> 6);
    const int h  = (bid >> 2) & 15;
    const int b  = bid & 3;
    const int kvh = h >> 2;
    const int m0 = mt * 128;
    const int wm = wid * 16;

    const int njt = (m0 >> 6) + 2;

    auto issue_kv = [&](int jt, int stg) {
        uint32_t sbase = sb + (uint32_t)(F_KV0 + stg * F_STAGE) * 2;
#pragma unroll
        for (int it = 0; it < 2; it++) {
            int idx = tid + it * 256;
            int r = idx >> 3;
            int c8 = (idx & 7) * 8;
            size_t g = (size_t)(b * T_ + jt * 64 + r) * KVD + kvh * DK + c8;
            uint32_t so = sbase + (uint32_t)(r * FLD + c8) * 2;
            CP_ASYNC16(so + SK_HI * 2, Khi + g);
            CP_ASYNC16(so + SV_HI * 2, Vhi + g);
        }
        CP_COMMIT();
    };

    issue_kv(0, 0);
    issue_kv(1, 1);        // njt >= 2 always

#pragma unroll
    for (int it = 0; it < 2; it++) {
        int idx = tid + it * 256;
        int r = idx >> 2;
        int c8 = (idx & 3) * 16;
        size_t g = (size_t)(b * T_ + m0 + r) * DM + h * DK + c8;
        *(uint4*)(fsm + F_QHI + r * FLD + c8)     = *(const uint4*)(Qhi + g);
        *(uint4*)(fsm + F_QHI + r * FLD + c8 + 8) = *(const uint4*)(Qhi + g + 8);
    }
    __syncthreads();

    uint32_t qh[4][4];
    {
        const int qrow = wm + (lane & 15);
        const int qcolp = (lane >> 4) * 8;
#pragma unroll
        for (int kk = 0; kk < 4; kk++) {
            uint32_t addr = sb + (uint32_t)(F_QHI + qrow * FLD + kk * 16 + qcolp) * 2;
            LDSM4(qh[kk][0], qh[kk][1], qh[kk][2], qh[kk][3], addr);
        }
    }

    float oa[8][4];
#pragma unroll
    for (int ns = 0; ns < 8; ns++)
#pragma unroll
        for (int q = 0; q < 4; q++) oa[ns][q] = 0.f;
    float rm0 = -1e30f, rm1 = -1e30f, rs0 = 0.f, rs1 = 0.f;

    const int row_lo = lane >> 2;
    const int col_lo = (lane & 3) * 2;

    for (int jt = 0; jt < njt; jt++) {
        const int n0 = jt * 64;
        if (jt + 2 < njt) {
            issue_kv(jt + 2, (jt + 2) % 3);
            CP_WAIT(2);
        } else if (jt + 1 < njt) {
            CP_WAIT(1);
        } else {
            CP_WAIT(0);
        }
        __syncthreads();
        const uint32_t kvb = sb + (uint32_t)(F_KV0 + (jt % 3) * F_STAGE) * 2;

        if (n0 <= m0 + wm + 15) {
            float s[8][4];
#pragma unroll
            for (int ns = 0; ns < 8; ns++)
#pragma unroll
                for (int q = 0; q < 4; q++) s[ns][q] = 0.f;

            const int kb_row  = ((lane >> 4) << 3) + (lane & 7);
            const int kb_colp = ((lane >> 3) & 1) * 8;
#pragma unroll
            for (int kk = 0; kk < 4; kk++) {
#pragma unroll
                for (int np = 0; np < 4; np++) {
                    uint32_t addr = kvb + (uint32_t)((np * 16 + kb_row) * FLD +
                                                     kk * 16 + kb_colp) * 2;
                    uint32_t bh[4];
                    LDSM4(bh[0], bh[1], bh[2], bh[3], addr + SK_HI * 2);
                    mma_f16(s[2 * np],     qh[kk], bh);
                    mma_f16(s[2 * np + 1], qh[kk], bh + 2);
                }
            }

            if (n0 + 63 > m0 + wm) {
                const int r0 = m0 + wm + row_lo;
#pragma unroll
                for (int ns = 0; ns < 8; ns++) {
                    int col = n0 + ns * 8 + col_lo;
                    if (col > r0)         s[ns][0] = -1e30f;
                    if (col + 1 > r0)     s[ns][1] = -1e30f;
                    if (col > r0 + 8)     s[ns][2] = -1e30f;
                    if (col + 1 > r0 + 8) s[ns][3] = -1e30f;
                }
            }

            float mx0 = -1e30f, mx1 = -1e30f;
#pragma unroll
            for (int ns = 0; ns < 8; ns++) {
                mx0 = fmaxf(mx0, fmaxf(s[ns][0], s[ns][1]));
                mx1 = fmaxf(mx1, fmaxf(s[ns][2], s[ns][3]));
            }
            mx0 = fmaxf(mx0, __shfl_xor_sync(0xffffffffu, mx0, 1));
            mx0 = fmaxf(mx0, __shfl_xor_sync(0xffffffffu, mx0, 2));
            mx1 = fmaxf(mx1, __shfl_xor_sync(0xffffffffu, mx1, 1));
            mx1 = fmaxf(mx1, __shfl_xor_sync(0xffffffffu, mx1, 2));
            float mn0 = fmaxf(rm0, mx0), mn1 = fmaxf(rm1, mx1);
            float al0 = exp2f(rm0 - mn0), al1 = exp2f(rm1 - mn1);
            rm0 = mn0; rm1 = mn1;
            float ps0 = 0.f, ps1 = 0.f;
#pragma unroll
            for (int ns = 0; ns < 8; ns++) {
                s[ns][0] = exp2f(s[ns][0] - mn0);
                s[ns][1] = exp2f(s[ns][1] - mn0);
                s[ns][2] = exp2f(s[ns][2] - mn1);
                s[ns][3] = exp2f(s[ns][3] - mn1);
                ps0 += s[ns][0] + s[ns][1];
                ps1 += s[ns][2] + s[ns][3];
            }
            ps0 += __shfl_xor_sync(0xffffffffu, ps0, 1);
            ps0 += __shfl_xor_sync(0xffffffffu, ps0, 2);
            ps1 += __shfl_xor_sync(0xffffffffu, ps1, 1);
            ps1 += __shfl_xor_sync(0xffffffffu, ps1, 2);
            rs0 = rs0 * al0 + ps0;
            rs1 = rs1 * al1 + ps1;
#pragma unroll
            for (int ns = 0; ns < 8; ns++) {
                oa[ns][0] *= al0; oa[ns][1] *= al0;
                oa[ns][2] *= al1; oa[ns][3] *= al1;
            }

            uint32_t ph[4][4];
#pragma unroll
            for (int kk2 = 0; kk2 < 4; kk2++) {
                ph[kk2][0] = pack_hi(s[2 * kk2][0],     s[2 * kk2][1]);
                ph[kk2][1] = pack_hi(s[2 * kk2][2],     s[2 * kk2][3]);
                ph[kk2][2] = pack_hi(s[2 * kk2 + 1][0], s[2 * kk2 + 1][1]);
                ph[kk2][3] = pack_hi(s[2 * kk2 + 1][2], s[2 * kk2 + 1][3]);
            }

            const int v_row = lane & 15;
            const int v_colp = (lane >> 4) * 8;
#pragma unroll
            for (int kk2 = 0; kk2 < 4; kk2++) {
#pragma unroll
                for (int np = 0; np < 4; np++) {
                    uint32_t addr = kvb + (uint32_t)((kk2 * 16 + v_row) * FLD +
                                                     np * 16 + v_colp) * 2;
                    uint32_t bh[4];
                    LDSM4T(bh[0], bh[1], bh[2], bh[3], addr + SV_HI * 2);
                    mma_f16(oa[2 * np],     ph[kk2], bh);
                    mma_f16(oa[2 * np + 1], ph[kk2], bh + 2);
                }
            }
        }
        __syncthreads();
    }

    float inv0 = 1.f / rs0, inv1 = 1.f / rs1;
    int r0 = m0 + wm + row_lo;
#pragma unroll
    for (int ns = 0; ns < 8; ns++) {
        size_t idx0 = (size_t)(b * T_ + r0) * DM + h * DK + ns * 8 + col_lo;
        size_t idx1 = idx0 + (size_t)8 * DM;
        *(uint32_t*)(Ohi + idx0) = pack_hi(oa[ns][0] * inv0, oa[ns][1] * inv0);
        *(uint32_t*)(Ohi + idx1) = pack_hi(oa[ns][2] * inv1, oa[ns][3] * inv1);
    }
}

// ---------------- launch ----------------
extern "C" void kernel_launch(void* const* d_in, const int* in_sizes, int n_in,
                              void* d_out, int out_size) {
    (void)in_sizes; (void)n_in; (void)out_size;
    const float* x  = (const float*)d_in[0];
    const float* Wq = (const float*)d_in[2];
    const float* Wk = (const float*)d_in[3];
    const float* Wv = (const float*)d_in[4];
    const float* Wo = (const float*)d_in[5];
    float* out = (float*)d_out;

    __half *Xhi, *Ahi, *Qhi, *Khi, *Vhi, *Wall;
    cudaGetSymbolAddress((void**)&Xhi, g_Xhi);
    cudaGetSymbolAddress((void**)&Ahi, g_Ahi);
    cudaGetSymbolAddress((void**)&Qhi, g_Qhi);
    cudaGetSymbolAddress((void**)&Khi, g_Khi);
    cudaGetSymbolAddress((void**)&Vhi, g_Vhi);
    cudaGetSymbolAddress((void**)&Wall, g_Wall);

    static bool attr_set = false;
    if (!attr_set) {
        cudaFuncSetAttribute(gemm_qkv, cudaFuncAttributeMaxDynamicSharedMemorySize, GEMM_SMEM);
        cudaFuncSetAttribute(gemm_mma, cudaFuncAttributeMaxDynamicSharedMemorySize, GEMM_SMEM);
        cudaFuncSetAttribute(flash_mma, cudaFuncAttributeMaxDynamicSharedMemorySize, FLASH_SMEM);
        attr_set = true;
    }

    rope_table_kernel<<<(T_ * 32) / 256, 256>>>();
    cvt_hi8<<<(ROWS * DM / 8) / 256, 256>>>(x, Xhi, ROWS * DM / 8);
    cvt_w_all<<<dim3(NWALL / 32, DM / 32), dim3(32, 8)>>>(Wq, Wk, Wv, Wo, Wall);

    gemm_qkv<<<dim3(NQKV / 128, ROWS / 128), 256, GEMM_SMEM>>>(
        Xhi, Wall, Qhi, Khi, Vhi);

    flash_mma<<<dim3(16 * NH * B_), 256, FLASH_SMEM>>>(
        Qhi, Khi, Vhi, Ahi);

    gemm_mma<<<dim3(DM / 128, ROWS / 128), 256, GEMM_SMEM>>>(
        Ahi, Wall + (size_t)NQKV * DM, out, ROWS, DM, DM);
}